// round 15
// baseline (speedup 1.0000x reference)
#include <cuda_runtime.h>
#include <cuda_bf16.h>
#include <math.h>
#include <stdint.h>

#define BB   1024
#define IND  256
#define LATD 512
#define HIDD 1024
#define OUTD 64
#define NSTEPS 20

#define TM 64
#define TN 64
#define BK 32
#define THREADS 256
#define NCTA 128

// ---------------- device scratch (no allocation allowed) ----------------
__device__ float g_h[BB * LATD];
__device__ float g_acc[BB * LATD];
__device__ __nv_bfloat16 g_xh[BB * IND],  g_xl[BB * IND];
__device__ __nv_bfloat16 g_hh[BB * LATD], g_hl[BB * LATD];
__device__ __nv_bfloat16 g_th[BB * LATD], g_tl[BB * LATD];
__device__ __nv_bfloat16 g_Gh[BB * HIDD], g_Gl[BB * HIDD];
__device__ __nv_bfloat16 g_W1h[HIDD * LATD], g_W1l[HIDD * LATD];   // [N=1024, K=512]
__device__ __nv_bfloat16 g_W2h[LATD * HIDD], g_W2l[LATD * HIDD];   // [N=512,  K=1024]
__device__ __nv_bfloat16 g_Wih[LATD * IND],  g_Wil[LATD * IND];    // [N=512,  K=256]
__device__ __nv_bfloat16 g_Woh[OUTD * (LATD/2)], g_Wol[OUTD * (LATD/2)]; // [64,256]

// grid-barrier state (persists across graph replays; generation-based)
__device__ int g_gen = 0;
__device__ int g_cnt = 0;

__device__ __forceinline__ uint32_t smem_u32(const void* p) {
    uint32_t a;
    asm("{ .reg .u64 t; cvta.to.shared.u64 t, %1; cvt.u32.u64 %0, t; }" : "=r"(a) : "l"(p));
    return a;
}

#define LDMX4(r0, r1, r2, r3, addr)                                               \
    asm volatile("ldmatrix.sync.aligned.m8n8.x4.shared.b16 {%0,%1,%2,%3}, [%4];"  \
        : "=r"(r0), "=r"(r1), "=r"(r2), "=r"(r3) : "r"(addr))

#define MMA16816(d, a, b0v, b1v)                                                  \
    asm volatile("mma.sync.aligned.m16n8k16.row.col.f32.bf16.bf16.f32 "           \
        "{%0,%1,%2,%3}, {%4,%5,%6,%7}, {%8,%9}, {%0,%1,%2,%3};"                   \
        : "+f"((d)[0]), "+f"((d)[1]), "+f"((d)[2]), "+f"((d)[3])                  \
        : "r"((a)[0]), "r"((a)[1]), "r"((a)[2]), "r"((a)[3]), "r"(b0v), "r"(b1v))

// smem staging: 64 rows x 80 B per tile-operand, hi/lo, 2 stages = 40960 B
#define TS_B (TM * 80)           // 5120
#define SM_AH(s) ((s) * TS_B)
#define SM_AL(s) (2 * TS_B + (s) * TS_B)
#define SM_BH(s) (4 * TS_B + (s) * TS_B)
#define SM_BL(s) (6 * TS_B + (s) * TS_B)
#define SMEM_BYTES (8 * TS_B)    // 40960

__device__ __forceinline__ void store_split(__nv_bfloat16* Oh, __nv_bfloat16* Ol,
                                            size_t idx, float a, float b) {
    __nv_bfloat16 ah = __float2bfloat16(a);
    __nv_bfloat16 bh = __float2bfloat16(b);
    __nv_bfloat162 hv; hv.x = ah; hv.y = bh;
    *reinterpret_cast<__nv_bfloat162*>(Oh + idx) = hv;
    __nv_bfloat162 lv;
    lv.x = __float2bfloat16(a - __bfloat162float(ah));
    lv.y = __float2bfloat16(b - __bfloat162float(bh));
    *reinterpret_cast<__nv_bfloat162*>(Ol + idx) = lv;
}

// EPI modes: 0 tanh(+time bias), 1 k1, 2 k2/k3, 3 k4+state update, 4 plain
template <int EPI>
__device__ __forceinline__ void epi_pair(int m, int n, float v0, float v1,
    const float* __restrict__ bias, const float* __restrict__ bias2, float b2s,
    float* __restrict__ Cf, int ldc,
    __nv_bfloat16* __restrict__ Oh, __nv_bfloat16* __restrict__ Ol, int ldo,
    float* __restrict__ accb, const float* __restrict__ hbase,
    float wk, float cstep, float s6)
{
    if (EPI == 0) {
        v0 = tanhf(v0 + bias[n]     + b2s * bias2[n]);
        v1 = tanhf(v1 + bias[n + 1] + b2s * bias2[n + 1]);
        if (Cf) {
            float2 f; f.x = v0; f.y = v1;
            *reinterpret_cast<float2*>(Cf + (size_t)m * ldc + n) = f;
        }
        store_split(Oh, Ol, (size_t)m * ldo + n, v0, v1);
    } else if (EPI == 4) {
        float2 f; f.x = v0 + bias[n]; f.y = v1 + bias[n + 1];
        *reinterpret_cast<float2*>(Cf + (size_t)m * ldc + n) = f;
    } else {
        const size_t idx = (size_t)m * ldo + n;
        const float k0v = v0 + bias[n];
        const float k1v = v1 + bias[n + 1];
        float a0, a1;
        if (EPI == 1) { a0 = k0v; a1 = k1v; accb[idx] = a0; accb[idx + 1] = a1; }
        else          { a0 = accb[idx] + wk * k0v; a1 = accb[idx + 1] + wk * k1v;
                        if (EPI == 2) { accb[idx] = a0; accb[idx + 1] = a1; } }
        const float h0v = hbase[idx], h1v = hbase[idx + 1];
        float o0, o1;
        if (EPI == 3) {
            o0 = h0v + s6 * a0;
            o1 = h1v + s6 * a1;
            float2 f; f.x = o0; f.y = o1;
            *reinterpret_cast<float2*>(Cf + idx) = f;
        } else {
            o0 = h0v + cstep * k0v;
            o1 = h1v + cstep * k1v;
        }
        store_split(Oh, Ol, idx, o0, o1);
    }
}

// One 64x64 output tile of  C = A[BMxK] * B[K x TN (B stored [N,K])], split-bf16 3-term.
template <int EPI>
__device__ void gemm_tile(char* smem,
    const __nv_bfloat16* __restrict__ Ah, const __nv_bfloat16* __restrict__ Al,
    int lda, int K,
    const __nv_bfloat16* __restrict__ Bh, const __nv_bfloat16* __restrict__ Bl,
    const float* __restrict__ bias, const float* __restrict__ bias2, float b2s,
    float* __restrict__ Cf, int ldc,
    __nv_bfloat16* __restrict__ Oh, __nv_bfloat16* __restrict__ Ol, int ldo,
    float* __restrict__ accb, const float* __restrict__ hbase,
    float wk, float cstep, float s6,
    int bm0, int bn0)
{
    const uint32_t sb = smem_u32(smem);
    const int tid = threadIdx.x;
    const int wid = tid >> 5, lane = tid & 31;
    const int wm = (wid & 1) * 32;          // warp M offset (2 warps in M)
    const int wn = (wid >> 1) * 16;         // warp N offset (4 warps in N)
    const int lgrp = lane >> 3, lrow = lane & 7;

    const int row = tid >> 2, kq = tid & 3;  // staging: row 0..63, 16B quad 0..3

    float acc[2][2][4];
#pragma unroll
    for (int i = 0; i < 2; i++)
#pragma unroll
        for (int j = 0; j < 2; j++)
#pragma unroll
            for (int k = 0; k < 4; k++) acc[i][j][k] = 0.0f;

    // preload chunk 0 into stage 0
    {
        uint4 avh = *reinterpret_cast<const uint4*>(Ah + (size_t)(bm0 + row) * lda + kq * 8);
        uint4 avl = *reinterpret_cast<const uint4*>(Al + (size_t)(bm0 + row) * lda + kq * 8);
        uint4 bvh = *reinterpret_cast<const uint4*>(Bh + (size_t)(bn0 + row) * K + kq * 8);
        uint4 bvl = *reinterpret_cast<const uint4*>(Bl + (size_t)(bn0 + row) * K + kq * 8);
        *reinterpret_cast<uint4*>(smem + SM_AH(0) + row * 80 + kq * 16) = avh;
        *reinterpret_cast<uint4*>(smem + SM_AL(0) + row * 80 + kq * 16) = avl;
        *reinterpret_cast<uint4*>(smem + SM_BH(0) + row * 80 + kq * 16) = bvh;
        *reinterpret_cast<uint4*>(smem + SM_BL(0) + row * 80 + kq * 16) = bvl;
    }
    __syncthreads();

    const int nc = K / BK;
    for (int c = 0; c < nc; c++) {
        const int s = c & 1;
        const bool pre = (c + 1 < nc);
        uint4 avh, avl, bvh, bvl;
        if (pre) {
            const int k0 = (c + 1) * BK;
            avh = *reinterpret_cast<const uint4*>(Ah + (size_t)(bm0 + row) * lda + k0 + kq * 8);
            avl = *reinterpret_cast<const uint4*>(Al + (size_t)(bm0 + row) * lda + k0 + kq * 8);
            bvh = *reinterpret_cast<const uint4*>(Bh + (size_t)(bn0 + row) * K + k0 + kq * 8);
            bvl = *reinterpret_cast<const uint4*>(Bl + (size_t)(bn0 + row) * K + k0 + kq * 8);
        }

#pragma unroll
        for (int ks = 0; ks < 2; ks++) {
            uint32_t ahf[2][4], alf[2][4], bhf[4], blf[4];
            const int acol = (ks * 16 + (lgrp >> 1) * 8) * 2;
            const int bcol = (ks * 16 + (lgrp & 1) * 8) * 2;
#pragma unroll
            for (int mt = 0; mt < 2; mt++) {
                const int ar = wm + mt * 16 + (lgrp & 1) * 8 + lrow;
                LDMX4(ahf[mt][0], ahf[mt][1], ahf[mt][2], ahf[mt][3], sb + SM_AH(s) + ar * 80 + acol);
                LDMX4(alf[mt][0], alf[mt][1], alf[mt][2], alf[mt][3], sb + SM_AL(s) + ar * 80 + acol);
            }
            {
                const int br = wn + (lgrp >> 1) * 8 + lrow;
                LDMX4(bhf[0], bhf[1], bhf[2], bhf[3], sb + SM_BH(s) + br * 80 + bcol);
                LDMX4(blf[0], blf[1], blf[2], blf[3], sb + SM_BL(s) + br * 80 + bcol);
            }
#pragma unroll
            for (int mt = 0; mt < 2; mt++)
#pragma unroll
                for (int nt = 0; nt < 2; nt++) {
                    const int o = nt * 2;
                    MMA16816(acc[mt][nt], ahf[mt], bhf[o], bhf[o + 1]);
                    MMA16816(acc[mt][nt], ahf[mt], blf[o], blf[o + 1]);
                    MMA16816(acc[mt][nt], alf[mt], bhf[o], bhf[o + 1]);
                }
        }

        if (pre) {
            const int sn = s ^ 1;
            *reinterpret_cast<uint4*>(smem + SM_AH(sn) + row * 80 + kq * 16) = avh;
            *reinterpret_cast<uint4*>(smem + SM_AL(sn) + row * 80 + kq * 16) = avl;
            *reinterpret_cast<uint4*>(smem + SM_BH(sn) + row * 80 + kq * 16) = bvh;
            *reinterpret_cast<uint4*>(smem + SM_BL(sn) + row * 80 + kq * 16) = bvl;
        }
        __syncthreads();
    }

#pragma unroll
    for (int mt = 0; mt < 2; mt++)
#pragma unroll
        for (int nt = 0; nt < 2; nt++) {
            const int m0 = bm0 + wm + mt * 16 + (lane >> 2);
            const int n  = bn0 + wn + nt * 8 + (lane & 3) * 2;
            epi_pair<EPI>(m0,     n, acc[mt][nt][0], acc[mt][nt][1],
                          bias, bias2, b2s, Cf, ldc, Oh, Ol, ldo, accb, hbase, wk, cstep, s6);
            epi_pair<EPI>(m0 + 8, n, acc[mt][nt][2], acc[mt][nt][3],
                          bias, bias2, b2s, Cf, ldc, Oh, Ol, ldo, accb, hbase, wk, cstep, s6);
        }
}

// generation-based grid barrier; gen0 snapshotted before first arrive (replay-safe)
__device__ __forceinline__ void grid_barrier(int tid, int gen0, int idx) {
    __syncthreads();
    __threadfence();
    if (tid == 0) {
        int old = atomicAdd(&g_cnt, 1);
        if (old == NCTA - 1) {
            atomicExch(&g_cnt, 0);
            __threadfence();
            atomicAdd(&g_gen, 1);
        } else {
            while (*(volatile int*)&g_gen - gen0 < idx) __nanosleep(64);
        }
        __threadfence();
    }
    __syncthreads();
}

__global__ __launch_bounds__(THREADS, 1)
void ode_mega(
    const __nv_bfloat16* __restrict__ xh, const __nv_bfloat16* __restrict__ xl,
    const __nv_bfloat16* __restrict__ Wih, const __nv_bfloat16* __restrict__ Wil,
    const float* __restrict__ b_in,
    const __nv_bfloat16* __restrict__ W1h, const __nv_bfloat16* __restrict__ W1l,
    const float* __restrict__ b1, const float* __restrict__ W1t,
    const __nv_bfloat16* __restrict__ W2h, const __nv_bfloat16* __restrict__ W2l,
    const float* __restrict__ b2,
    const __nv_bfloat16* __restrict__ Woh, const __nv_bfloat16* __restrict__ Wol,
    const float* __restrict__ b_out,
    float* __restrict__ h, float* __restrict__ acc,
    __nv_bfloat16* __restrict__ hh, __nv_bfloat16* __restrict__ hl,
    __nv_bfloat16* __restrict__ th, __nv_bfloat16* __restrict__ tl,
    __nv_bfloat16* __restrict__ Gh, __nv_bfloat16* __restrict__ Gl,
    float* __restrict__ out)
{
    __shared__ char smem[SMEM_BYTES];
    __shared__ int s_gen0;
    const int tid = threadIdx.x;
    const int bid = blockIdx.x;

    if (tid == 0) s_gen0 = *(volatile int*)&g_gen;
    __syncthreads();
    const int gen0 = s_gen0;
    int nbar = 0;

    const float dt = 1.0f / (float)NSTEPS;
    const float s6 = dt / 6.0f;

    // ---- phase: h0 = tanh(x @ W_in + b_in) ; 128 tiles (16 x 8) ----
    {
        const int tm = bid >> 3, tn = bid & 7;
        gemm_tile<0>(smem, xh, xl, IND, IND, Wih, Wil,
                     b_in, b_in, 0.0f, h, LATD, hh, hl, LATD,
                     nullptr, nullptr, 0.f, 0.f, s6, tm * TM, tn * TN);
    }
    grid_barrier(tid, gen0, ++nbar);

    for (int step = 0; step < NSTEPS; step++) {
        const float t = dt * (float)step;
#pragma unroll
        for (int sub = 0; sub < 4; sub++) {
            const float tsub = (sub == 0) ? t : (sub == 3 ? t + dt : t + 0.5f * dt);
            const float cstep = (sub == 0 || sub == 1) ? 0.5f * dt : (sub == 2 ? dt : 0.0f);
            const float wkv = (sub == 1 || sub == 2) ? 2.0f : 1.0f;

            const __nv_bfloat16* dih = (sub == 0) ? hh : th;
            const __nv_bfloat16* dil = (sub == 0) ? hl : tl;

            // ---- GEMM1: G = tanh(dyn_in @ W1[:512] + b1 + tsub*W1[512,:]) ----
            // 256 tiles (16 x 16): CTA does tiles bid and bid+128
#pragma unroll
            for (int tt = 0; tt < 2; tt++) {
                const int tile = bid + tt * NCTA;
                const int tm = tile >> 4, tn = tile & 15;
                gemm_tile<0>(smem, dih, dil, LATD, LATD, W1h, W1l,
                             b1, W1t, tsub, nullptr, 0, Gh, Gl, HIDD,
                             nullptr, nullptr, 0.f, 0.f, s6, tm * TM, tn * TN);
            }
            grid_barrier(tid, gen0, ++nbar);

            // ---- GEMM2: k = G @ W2 + b2 with fused RK4 ; 128 tiles (16 x 8) ----
            {
                const int tm = bid >> 3, tn = bid & 7;
                if (sub == 0) {
                    gemm_tile<1>(smem, Gh, Gl, HIDD, HIDD, W2h, W2l,
                                 b2, b2, 0.f, nullptr, 0, th, tl, LATD,
                                 acc, h, 1.0f, cstep, s6, tm * TM, tn * TN);
                } else if (sub < 3) {
                    gemm_tile<2>(smem, Gh, Gl, HIDD, HIDD, W2h, W2l,
                                 b2, b2, 0.f, nullptr, 0, th, tl, LATD,
                                 acc, h, wkv, cstep, s6, tm * TM, tn * TN);
                } else {
                    gemm_tile<3>(smem, Gh, Gl, HIDD, HIDD, W2h, W2l,
                                 b2, b2, 0.f, h, LATD, hh, hl, LATD,
                                 acc, h, 1.0f, 0.f, s6, tm * TM, tn * TN);
                }
            }
            grid_barrier(tid, gen0, ++nbar);
        }
    }

    // ---- phase: out = h[:, :256] @ W_out + b_out ; 16 tiles (16 x 1) ----
    if (bid < 16) {
        gemm_tile<4>(smem, hh, hl, LATD, LATD / 2, Woh, Wol,
                     b_out, b_out, 0.f, out, OUTD, nullptr, nullptr, 0,
                     nullptr, nullptr, 0.f, 0.f, s6, bid * TM, 0);
    }
}

// ---------------- prep kernels ----------------
__global__ void k_split(const float* __restrict__ src,
                        __nv_bfloat16* __restrict__ h, __nv_bfloat16* __restrict__ l, int n) {
    int i = blockIdx.x * blockDim.x + threadIdx.x;
    if (i < n) {
        float v = src[i];
        __nv_bfloat16 hi = __float2bfloat16(v);
        h[i] = hi;
        l[i] = __float2bfloat16(v - __bfloat162float(hi));
    }
}
__global__ void k_splitT(const float* __restrict__ W, int K, int N,
                         __nv_bfloat16* __restrict__ Th, __nv_bfloat16* __restrict__ Tl) {
    int i = blockIdx.x * blockDim.x + threadIdx.x;
    if (i < K * N) {
        int k = i / N, n = i - k * N;
        float v = W[i];
        __nv_bfloat16 hi = __float2bfloat16(v);
        Th[(size_t)n * K + k] = hi;
        Tl[(size_t)n * K + k] = __float2bfloat16(v - __bfloat162float(hi));
    }
}

// ---------------- host ----------------
extern "C" void kernel_launch(void* const* d_in, const int* in_sizes, int n_in,
                              void* d_out, int out_size)
{
    const float* x     = (const float*)d_in[0];
    const float* W_in  = (const float*)d_in[1];
    const float* b_in  = (const float*)d_in[2];
    const float* W1    = (const float*)d_in[3];  // (513, 1024)
    const float* b1    = (const float*)d_in[4];
    const float* W2    = (const float*)d_in[5];  // (1024, 512)
    const float* b2    = (const float*)d_in[6];
    const float* W_out = (const float*)d_in[7];  // (256, 64)
    const float* b_out = (const float*)d_in[8];
    float* out = (float*)d_out;

    float *h, *acc;
    __nv_bfloat16 *xh, *xl, *hh, *hl, *th, *tl, *Gh, *Gl;
    __nv_bfloat16 *W1h, *W1l, *W2h, *W2l, *Wih, *Wil, *Woh, *Wol;
    cudaGetSymbolAddress((void**)&h,   g_h);
    cudaGetSymbolAddress((void**)&acc, g_acc);
    cudaGetSymbolAddress((void**)&xh,  g_xh);  cudaGetSymbolAddress((void**)&xl,  g_xl);
    cudaGetSymbolAddress((void**)&hh,  g_hh);  cudaGetSymbolAddress((void**)&hl,  g_hl);
    cudaGetSymbolAddress((void**)&th,  g_th);  cudaGetSymbolAddress((void**)&tl,  g_tl);
    cudaGetSymbolAddress((void**)&Gh,  g_Gh);  cudaGetSymbolAddress((void**)&Gl,  g_Gl);
    cudaGetSymbolAddress((void**)&W1h, g_W1h); cudaGetSymbolAddress((void**)&W1l, g_W1l);
    cudaGetSymbolAddress((void**)&W2h, g_W2h); cudaGetSymbolAddress((void**)&W2l, g_W2l);
    cudaGetSymbolAddress((void**)&Wih, g_Wih); cudaGetSymbolAddress((void**)&Wil, g_Wil);
    cudaGetSymbolAddress((void**)&Woh, g_Woh); cudaGetSymbolAddress((void**)&Wol, g_Wol);

    const float* W1t = W1 + (size_t)LATD * HIDD;  // fp32 time-column weights (row 512)

    // prep: split inputs / split+transpose weights
    k_split<<<(BB * IND + 255) / 256, 256>>>(x, xh, xl, BB * IND);
    k_splitT<<<(IND * LATD + 255) / 256, 256>>>(W_in, IND, LATD, Wih, Wil);
    k_splitT<<<(LATD * HIDD + 255) / 256, 256>>>(W1, LATD, HIDD, W1h, W1l);
    k_splitT<<<(HIDD * LATD + 255) / 256, 256>>>(W2, HIDD, LATD, W2h, W2l);
    k_splitT<<<((LATD / 2) * OUTD + 255) / 256, 256>>>(W_out, LATD / 2, OUTD, Woh, Wol);

    // single persistent megakernel for the whole ODE solve
    ode_mega<<<NCTA, THREADS>>>(
        xh, xl, Wih, Wil, b_in,
        W1h, W1l, b1, W1t,
        W2h, W2l, b2,
        Woh, Wol, b_out,
        h, acc, hh, hl, th, tl, Gh, Gl, out);
}

// round 17
// speedup vs baseline: 1.2825x; 1.2825x over previous
#include <cuda_runtime.h>
#include <cuda_bf16.h>
#include <math.h>
#include <stdint.h>

#define BB   1024
#define IND  256
#define LATD 512
#define HIDD 1024
#define OUTD 64
#define NSTEPS 20

#define TM 64
#define TN 64
#define BK 32
#define THREADS 128

// ---------------- device scratch (no allocation allowed) ----------------
__device__ float g_h[BB * LATD];
__device__ float g_acc[BB * LATD];
__device__ __nv_bfloat16 g_xh[BB * IND],  g_xl[BB * IND];
__device__ __nv_bfloat16 g_hh[BB * LATD], g_hl[BB * LATD];
__device__ __nv_bfloat16 g_th[BB * LATD], g_tl[BB * LATD];
__device__ __nv_bfloat16 g_Gh[BB * HIDD], g_Gl[BB * HIDD];
__device__ __nv_bfloat16 g_W1h[HIDD * LATD], g_W1l[HIDD * LATD];   // [N=1024, K=512]
__device__ __nv_bfloat16 g_W2h[LATD * HIDD], g_W2l[LATD * HIDD];   // [N=512,  K=1024]
__device__ __nv_bfloat16 g_Wih[LATD * IND],  g_Wil[LATD * IND];    // [N=512,  K=256]
__device__ __nv_bfloat16 g_Woh[OUTD * (LATD/2)], g_Wol[OUTD * (LATD/2)]; // [64,256]

__device__ __forceinline__ uint32_t smem_u32(const void* p) {
    uint32_t a;
    asm("{ .reg .u64 t; cvta.to.shared.u64 t, %1; cvt.u32.u64 %0, t; }" : "=r"(a) : "l"(p));
    return a;
}

#define LDMX4(r0, r1, r2, r3, addr)                                               \
    asm volatile("ldmatrix.sync.aligned.m8n8.x4.shared.b16 {%0,%1,%2,%3}, [%4];"  \
        : "=r"(r0), "=r"(r1), "=r"(r2), "=r"(r3) : "r"(addr))

#define MMA16816(d, a, b0v, b1v)                                                  \
    asm volatile("mma.sync.aligned.m16n8k16.row.col.f32.bf16.bf16.f32 "           \
        "{%0,%1,%2,%3}, {%4,%5,%6,%7}, {%8,%9}, {%0,%1,%2,%3};"                   \
        : "+f"((d)[0]), "+f"((d)[1]), "+f"((d)[2]), "+f"((d)[3])                  \
        : "r"((a)[0]), "r"((a)[1]), "r"((a)[2]), "r"((a)[3]), "r"(b0v), "r"(b1v))

// smem staging: 64 rows x 80 B per operand (A/B x hi/lo), 2 stages = 40960 B static
#define TS_B (TM * 80)           // 5120
#define SM_AH(s) ((s) * TS_B)
#define SM_AL(s) (2 * TS_B + (s) * TS_B)
#define SM_BH(s) (4 * TS_B + (s) * TS_B)
#define SM_BL(s) (6 * TS_B + (s) * TS_B)
#define SMEM_BYTES (8 * TS_B)    // 40960

__device__ __forceinline__ void store_split(__nv_bfloat16* Oh, __nv_bfloat16* Ol,
                                            size_t idx, float a, float b) {
    __nv_bfloat16 ah = __float2bfloat16(a);
    __nv_bfloat16 bh = __float2bfloat16(b);
    __nv_bfloat162 hv; hv.x = ah; hv.y = bh;
    *reinterpret_cast<__nv_bfloat162*>(Oh + idx) = hv;
    __nv_bfloat162 lv;
    lv.x = __float2bfloat16(a - __bfloat162float(ah));
    lv.y = __float2bfloat16(b - __bfloat162float(bh));
    *reinterpret_cast<__nv_bfloat162*>(Ol + idx) = lv;
}

// EPI modes: 0 tanh(+time bias), 1 k1, 2 k2/k3, 3 k4+state update, 4 plain
template <int EPI>
__device__ __forceinline__ void epi_pair(int m, int n, float v0, float v1,
    const float* __restrict__ bias, const float* __restrict__ bias2, float b2s,
    float* __restrict__ Cf, int ldc,
    __nv_bfloat16* __restrict__ Oh, __nv_bfloat16* __restrict__ Ol, int ldo,
    float* __restrict__ accb, const float* __restrict__ hbase,
    float wk, float cstep, float s6)
{
    if (EPI == 0) {
        v0 = tanhf(v0 + bias[n]     + b2s * bias2[n]);
        v1 = tanhf(v1 + bias[n + 1] + b2s * bias2[n + 1]);
        if (Cf) {
            float2 f; f.x = v0; f.y = v1;
            *reinterpret_cast<float2*>(Cf + (size_t)m * ldc + n) = f;
        }
        store_split(Oh, Ol, (size_t)m * ldo + n, v0, v1);
    } else if (EPI == 4) {
        float2 f; f.x = v0 + bias[n]; f.y = v1 + bias[n + 1];
        *reinterpret_cast<float2*>(Cf + (size_t)m * ldc + n) = f;
    } else {
        const size_t idx = (size_t)m * ldo + n;
        const float k0v = v0 + bias[n];
        const float k1v = v1 + bias[n + 1];
        float a0, a1;
        if (EPI == 1) { a0 = k0v; a1 = k1v; accb[idx] = a0; accb[idx + 1] = a1; }
        else          { a0 = accb[idx] + wk * k0v; a1 = accb[idx + 1] + wk * k1v;
                        if (EPI == 2) { accb[idx] = a0; accb[idx + 1] = a1; } }
        const float h0v = hbase[idx], h1v = hbase[idx + 1];
        float o0, o1;
        if (EPI == 3) {
            o0 = h0v + s6 * a0;
            o1 = h1v + s6 * a1;
            float2 f; f.x = o0; f.y = o1;
            *reinterpret_cast<float2*>(Cf + idx) = f;
        } else {
            o0 = h0v + cstep * k0v;
            o1 = h1v + cstep * k1v;
        }
        store_split(Oh, Ol, idx, o0, o1);
    }
}

// 64x64 tile GEMM: C = A[M,K] x B^T (B stored [N,K]); 4 warps, warp tile 32x32.
// Warp-level fragment code identical to the hw-validated R12 kernel.
template <int EPI>
__global__ __launch_bounds__(THREADS)
void mma_gemm(const __nv_bfloat16* __restrict__ Ah, const __nv_bfloat16* __restrict__ Al,
              int lda, int K,
              const __nv_bfloat16* __restrict__ Bh, const __nv_bfloat16* __restrict__ Bl,
              const float* __restrict__ bias, const float* __restrict__ bias2, float b2s,
              float* __restrict__ Cf, int ldc,
              __nv_bfloat16* __restrict__ Oh, __nv_bfloat16* __restrict__ Ol, int ldo,
              float* __restrict__ accb, const float* __restrict__ hbase,
              float wk, float cstep, float s6)
{
    __shared__ char smem[SMEM_BYTES];
    const uint32_t sb = smem_u32(smem);
    const int tid = threadIdx.x;
    const int wid = tid >> 5, lane = tid & 31;
    const int wm = (wid & 1) * 32;          // 2 warps in M
    const int wn = (wid >> 1) * 32;         // 2 warps in N
    const int lgrp = lane >> 3, lrow = lane & 7;
    const int bm0 = blockIdx.y * TM, bn0 = blockIdx.x * TN;

    float acc[2][4][4];
#pragma unroll
    for (int i = 0; i < 2; i++)
#pragma unroll
        for (int j = 0; j < 4; j++)
#pragma unroll
            for (int k = 0; k < 4; k++) acc[i][j][k] = 0.0f;

    // staging: 64x32 bf16 per operand = 256 uint4 slots; 128 threads x 2 slots
    const int row0 = tid >> 2,          kq0 = tid & 3;
    const int row1 = (tid + 128) >> 2,  kq1 = tid & 3;

    // preload chunk 0 -> stage 0
    {
        uint4 a0h = *reinterpret_cast<const uint4*>(Ah + (size_t)(bm0 + row0) * lda + kq0 * 8);
        uint4 a0l = *reinterpret_cast<const uint4*>(Al + (size_t)(bm0 + row0) * lda + kq0 * 8);
        uint4 a1h = *reinterpret_cast<const uint4*>(Ah + (size_t)(bm0 + row1) * lda + kq1 * 8);
        uint4 a1l = *reinterpret_cast<const uint4*>(Al + (size_t)(bm0 + row1) * lda + kq1 * 8);
        uint4 b0h = *reinterpret_cast<const uint4*>(Bh + (size_t)(bn0 + row0) * K + kq0 * 8);
        uint4 b0l = *reinterpret_cast<const uint4*>(Bl + (size_t)(bn0 + row0) * K + kq0 * 8);
        uint4 b1h = *reinterpret_cast<const uint4*>(Bh + (size_t)(bn0 + row1) * K + kq1 * 8);
        uint4 b1l = *reinterpret_cast<const uint4*>(Bl + (size_t)(bn0 + row1) * K + kq1 * 8);
        *reinterpret_cast<uint4*>(smem + SM_AH(0) + row0 * 80 + kq0 * 16) = a0h;
        *reinterpret_cast<uint4*>(smem + SM_AL(0) + row0 * 80 + kq0 * 16) = a0l;
        *reinterpret_cast<uint4*>(smem + SM_AH(0) + row1 * 80 + kq1 * 16) = a1h;
        *reinterpret_cast<uint4*>(smem + SM_AL(0) + row1 * 80 + kq1 * 16) = a1l;
        *reinterpret_cast<uint4*>(smem + SM_BH(0) + row0 * 80 + kq0 * 16) = b0h;
        *reinterpret_cast<uint4*>(smem + SM_BL(0) + row0 * 80 + kq0 * 16) = b0l;
        *reinterpret_cast<uint4*>(smem + SM_BH(0) + row1 * 80 + kq1 * 16) = b1h;
        *reinterpret_cast<uint4*>(smem + SM_BL(0) + row1 * 80 + kq1 * 16) = b1l;
    }
    __syncthreads();

    const int nc = K / BK;
    for (int c = 0; c < nc; c++) {
        const int s = c & 1;
        const bool pre = (c + 1 < nc);
        uint4 a0h, a0l, a1h, a1l, b0h, b0l, b1h, b1l;
        if (pre) {
            const int k0 = (c + 1) * BK;
            a0h = *reinterpret_cast<const uint4*>(Ah + (size_t)(bm0 + row0) * lda + k0 + kq0 * 8);
            a0l = *reinterpret_cast<const uint4*>(Al + (size_t)(bm0 + row0) * lda + k0 + kq0 * 8);
            a1h = *reinterpret_cast<const uint4*>(Ah + (size_t)(bm0 + row1) * lda + k0 + kq1 * 8);
            a1l = *reinterpret_cast<const uint4*>(Al + (size_t)(bm0 + row1) * lda + k0 + kq1 * 8);
            b0h = *reinterpret_cast<const uint4*>(Bh + (size_t)(bn0 + row0) * K + k0 + kq0 * 8);
            b0l = *reinterpret_cast<const uint4*>(Bl + (size_t)(bn0 + row0) * K + k0 + kq0 * 8);
            b1h = *reinterpret_cast<const uint4*>(Bh + (size_t)(bn0 + row1) * K + k0 + kq1 * 8);
            b1l = *reinterpret_cast<const uint4*>(Bl + (size_t)(bn0 + row1) * K + k0 + kq1 * 8);
        }

#pragma unroll
        for (int ks = 0; ks < 2; ks++) {
            uint32_t ahf[2][4], alf[2][4], bhf[2][4], blf[2][4];
            const int acol = (ks * 16 + (lgrp >> 1) * 8) * 2;
            const int bcol = (ks * 16 + (lgrp & 1) * 8) * 2;
#pragma unroll
            for (int mt = 0; mt < 2; mt++) {
                const int ar = wm + mt * 16 + (lgrp & 1) * 8 + lrow;
                LDMX4(ahf[mt][0], ahf[mt][1], ahf[mt][2], ahf[mt][3], sb + SM_AH(s) + ar * 80 + acol);
                LDMX4(alf[mt][0], alf[mt][1], alf[mt][2], alf[mt][3], sb + SM_AL(s) + ar * 80 + acol);
            }
#pragma unroll
            for (int ng = 0; ng < 2; ng++) {
                const int br = wn + ng * 16 + (lgrp >> 1) * 8 + lrow;
                LDMX4(bhf[ng][0], bhf[ng][1], bhf[ng][2], bhf[ng][3], sb + SM_BH(s) + br * 80 + bcol);
                LDMX4(blf[ng][0], blf[ng][1], blf[ng][2], blf[ng][3], sb + SM_BL(s) + br * 80 + bcol);
            }
#pragma unroll
            for (int mt = 0; mt < 2; mt++)
#pragma unroll
                for (int nt = 0; nt < 4; nt++) {
                    const int ng = nt >> 1, o = (nt & 1) * 2;
                    MMA16816(acc[mt][nt], ahf[mt], bhf[ng][o], bhf[ng][o + 1]);
                    MMA16816(acc[mt][nt], ahf[mt], blf[ng][o], blf[ng][o + 1]);
                    MMA16816(acc[mt][nt], alf[mt], bhf[ng][o], bhf[ng][o + 1]);
                }
        }

        if (pre) {
            const int sn = s ^ 1;
            *reinterpret_cast<uint4*>(smem + SM_AH(sn) + row0 * 80 + kq0 * 16) = a0h;
            *reinterpret_cast<uint4*>(smem + SM_AL(sn) + row0 * 80 + kq0 * 16) = a0l;
            *reinterpret_cast<uint4*>(smem + SM_AH(sn) + row1 * 80 + kq1 * 16) = a1h;
            *reinterpret_cast<uint4*>(smem + SM_AL(sn) + row1 * 80 + kq1 * 16) = a1l;
            *reinterpret_cast<uint4*>(smem + SM_BH(sn) + row0 * 80 + kq0 * 16) = b0h;
            *reinterpret_cast<uint4*>(smem + SM_BL(sn) + row0 * 80 + kq0 * 16) = b0l;
            *reinterpret_cast<uint4*>(smem + SM_BH(sn) + row1 * 80 + kq1 * 16) = b1h;
            *reinterpret_cast<uint4*>(smem + SM_BL(sn) + row1 * 80 + kq1 * 16) = b1l;
        }
        __syncthreads();
    }

#pragma unroll
    for (int mt = 0; mt < 2; mt++)
#pragma unroll
        for (int nt = 0; nt < 4; nt++) {
            const int m0 = bm0 + wm + mt * 16 + (lane >> 2);
            const int n  = bn0 + wn + nt * 8 + (lane & 3) * 2;
            epi_pair<EPI>(m0,     n, acc[mt][nt][0], acc[mt][nt][1],
                          bias, bias2, b2s, Cf, ldc, Oh, Ol, ldo, accb, hbase, wk, cstep, s6);
            epi_pair<EPI>(m0 + 8, n, acc[mt][nt][2], acc[mt][nt][3],
                          bias, bias2, b2s, Cf, ldc, Oh, Ol, ldo, accb, hbase, wk, cstep, s6);
        }
}

// ---------------- prep kernels ----------------
__global__ void k_split(const float* __restrict__ src,
                        __nv_bfloat16* __restrict__ h, __nv_bfloat16* __restrict__ l, int n) {
    int i = blockIdx.x * blockDim.x + threadIdx.x;
    if (i < n) {
        float v = src[i];
        __nv_bfloat16 hi = __float2bfloat16(v);
        h[i] = hi;
        l[i] = __float2bfloat16(v - __bfloat162float(hi));
    }
}
__global__ void k_splitT(const float* __restrict__ W, int K, int N,
                         __nv_bfloat16* __restrict__ Th, __nv_bfloat16* __restrict__ Tl) {
    int i = blockIdx.x * blockDim.x + threadIdx.x;
    if (i < K * N) {
        int k = i / N, n = i - k * N;
        float v = W[i];
        __nv_bfloat16 hi = __float2bfloat16(v);
        Th[(size_t)n * K + k] = hi;
        Tl[(size_t)n * K + k] = __float2bfloat16(v - __bfloat162float(hi));
    }
}

// ---------------- host ----------------
extern "C" void kernel_launch(void* const* d_in, const int* in_sizes, int n_in,
                              void* d_out, int out_size)
{
    const float* x     = (const float*)d_in[0];
    const float* W_in  = (const float*)d_in[1];
    const float* b_in  = (const float*)d_in[2];
    const float* W1    = (const float*)d_in[3];  // (513, 1024)
    const float* b1    = (const float*)d_in[4];
    const float* W2    = (const float*)d_in[5];  // (1024, 512)
    const float* b2    = (const float*)d_in[6];
    const float* W_out = (const float*)d_in[7];  // (256, 64)
    const float* b_out = (const float*)d_in[8];
    float* out = (float*)d_out;

    float *h, *acc;
    __nv_bfloat16 *xh, *xl, *hh, *hl, *th, *tl, *Gh, *Gl;
    __nv_bfloat16 *W1h, *W1l, *W2h, *W2l, *Wih, *Wil, *Woh, *Wol;
    cudaGetSymbolAddress((void**)&h,   g_h);
    cudaGetSymbolAddress((void**)&acc, g_acc);
    cudaGetSymbolAddress((void**)&xh,  g_xh);  cudaGetSymbolAddress((void**)&xl,  g_xl);
    cudaGetSymbolAddress((void**)&hh,  g_hh);  cudaGetSymbolAddress((void**)&hl,  g_hl);
    cudaGetSymbolAddress((void**)&th,  g_th);  cudaGetSymbolAddress((void**)&tl,  g_tl);
    cudaGetSymbolAddress((void**)&Gh,  g_Gh);  cudaGetSymbolAddress((void**)&Gl,  g_Gl);
    cudaGetSymbolAddress((void**)&W1h, g_W1h); cudaGetSymbolAddress((void**)&W1l, g_W1l);
    cudaGetSymbolAddress((void**)&W2h, g_W2h); cudaGetSymbolAddress((void**)&W2l, g_W2l);
    cudaGetSymbolAddress((void**)&Wih, g_Wih); cudaGetSymbolAddress((void**)&Wil, g_Wil);
    cudaGetSymbolAddress((void**)&Woh, g_Woh); cudaGetSymbolAddress((void**)&Wol, g_Wol);

    const float dt = 1.0f / (float)NSTEPS;
    const float s6 = dt / 6.0f;
    const float* W1t = W1 + (size_t)LATD * HIDD;  // fp32 time-column weights (row 512)

    // prep: split inputs / split+transpose weights
    k_split<<<(BB * IND + 255) / 256, 256>>>(x, xh, xl, BB * IND);
    k_splitT<<<(IND * LATD + 255) / 256, 256>>>(W_in, IND, LATD, Wih, Wil);
    k_splitT<<<(LATD * HIDD + 255) / 256, 256>>>(W1, LATD, HIDD, W1h, W1l);
    k_splitT<<<(HIDD * LATD + 255) / 256, 256>>>(W2, HIDD, LATD, W2h, W2l);
    k_splitT<<<((LATD / 2) * OUTD + 255) / 256, 256>>>(W_out, LATD / 2, OUTD, Woh, Wol);

    const dim3 blk(THREADS);
    const dim3 gr_h0(LATD / TN, BB / TM);   // (8, 16)  = 128 CTAs
    const dim3 gr_g1(HIDD / TN, BB / TM);   // (16, 16) = 256 CTAs
    const dim3 gr_g2(LATD / TN, BB / TM);   // (8, 16)  = 128 CTAs
    const dim3 gr_out(OUTD / TN, BB / TM);  // (1, 16)  = 16 CTAs

    // h0 = tanh(x @ W_in + b_in) -> h (fp32) + (hh, hl)
    mma_gemm<0><<<gr_h0, blk>>>(xh, xl, IND, IND, Wih, Wil,
        b_in, b_in, 0.0f, h, LATD, hh, hl, LATD, nullptr, nullptr, 0.f, 0.f, s6);

    for (int step = 0; step < NSTEPS; step++) {
        const float t = dt * (float)step;
        const float tsub[4] = {t, t + 0.5f * dt, t + 0.5f * dt, t + dt};
        const float csub[4] = {0.5f * dt, 0.5f * dt, dt, 0.0f};
        const float wsub[4] = {1.0f, 2.0f, 2.0f, 1.0f};

        for (int sub = 0; sub < 4; sub++) {
            const __nv_bfloat16* dih = (sub == 0) ? hh : th;
            const __nv_bfloat16* dil = (sub == 0) ? hl : tl;
            // G = tanh(dyn_in @ W1[:512] + b1 + t*W1[512,:]) -> (Gh, Gl)
            mma_gemm<0><<<gr_g1, blk>>>(dih, dil, LATD, LATD, W1h, W1l,
                b1, W1t, tsub[sub], nullptr, 0, Gh, Gl, HIDD, nullptr, nullptr, 0.f, 0.f, s6);
            // k = G @ W2 + b2 with fused RK4 bookkeeping
            if (sub == 0) {
                mma_gemm<1><<<gr_g2, blk>>>(Gh, Gl, HIDD, HIDD, W2h, W2l,
                    b2, b2, 0.f, nullptr, 0, th, tl, LATD, acc, h, 1.0f, csub[0], s6);
            } else if (sub < 3) {
                mma_gemm<2><<<gr_g2, blk>>>(Gh, Gl, HIDD, HIDD, W2h, W2l,
                    b2, b2, 0.f, nullptr, 0, th, tl, LATD, acc, h, wsub[sub], csub[sub], s6);
            } else {
                mma_gemm<3><<<gr_g2, blk>>>(Gh, Gl, HIDD, HIDD, W2h, W2l,
                    b2, b2, 0.f, h, LATD, hh, hl, LATD, acc, h, 1.0f, 0.f, s6);
            }
        }
    }

    // out = h[:, :256] @ W_out + b_out
    mma_gemm<4><<<gr_out, blk>>>(hh, hl, LATD, LATD / 2, Woh, Wol,
        b_out, b_out, 0.f, out, OUTD, nullptr, nullptr, 0, nullptr, nullptr, 0.f, 0.f, s6);
}